// round 8
// baseline (speedup 1.0000x reference)
#include <cuda_runtime.h>
#include <cuda_bf16.h>
#include <math.h>
#include <stdint.h>

// ---------------- problem-size maxima (fixed instance: T=4096,D=1024,F=4096,E=8,k=2)
#define T_MAX    4096
#define E_MAX    8
#define SLOT_MAX 2
#define D_MAX    1024
#define F_MAX    4096
#define RPAD_MAX (T_MAX * SLOT_MAX + E_MAX * 128)   // 9216
#define TILES_MAX (RPAD_MAX / 128)                  // 72

// ---------------- device scratch (static: no allocation anywhere)
__device__ float g_Xg [(size_t)RPAD_MAX * D_MAX];   // gathered tokens (tf32-rounded)
__device__ float g_H  [(size_t)RPAD_MAX * F_MAX];   // hidden (tf32-rounded)
__device__ float g_O  [(size_t)RPAD_MAX * D_MAX];   // expert outputs (fp32)
__device__ int   g_sel [T_MAX * SLOT_MAX];
__device__ float g_wts [T_MAX * SLOT_MAX];
__device__ int   g_pos [T_MAX * SLOT_MAX];
__device__ int   g_count [E_MAX];
__device__ int   g_cursor[E_MAX];
__device__ int   g_off   [E_MAX + 1];
__device__ int   g_tile2e[TILES_MAX];
__device__ int   g_row2tok[RPAD_MAX];

// ---------------- helpers ----------------
__device__ __forceinline__ float tf32r(float x) {
    uint32_t u;
    asm("cvt.rna.tf32.f32 %0, %1;" : "=r"(u) : "f"(x));
    return __uint_as_float(u);
}
__device__ __forceinline__ uint32_t tf32r_u(uint32_t x) {
    uint32_t u;
    asm("cvt.rna.tf32.f32 %0, %1;" : "=r"(u) : "f"(__uint_as_float(x)));
    return u;
}
__device__ __forceinline__ uint32_t smem_u32(const void* p) {
    uint32_t a;
    asm("{ .reg .u64 t; cvta.to.shared.u64 t, %1; cvt.u32.u64 %0, t; }" : "=r"(a) : "l"(p));
    return a;
}
__device__ __forceinline__ void cp16(uint32_t dst, const void* src) {
    asm volatile("cp.async.cg.shared.global [%0], [%1], 16;" :: "r"(dst), "l"(src));
}
__device__ __forceinline__ void cp16z(uint32_t dst, const void* src, int sz) {
    asm volatile("cp.async.cg.shared.global [%0], [%1], 16, %2;" :: "r"(dst), "l"(src), "r"(sz));
}
#define CP_COMMIT() asm volatile("cp.async.commit_group;" ::: "memory")
#define CP_WAIT1()  asm volatile("cp.async.wait_group 1;" ::: "memory")

__device__ __forceinline__ void mma16n8k8(float* c,
                                          uint32_t a0, uint32_t a1, uint32_t a2, uint32_t a3,
                                          uint32_t b0, uint32_t b1) {
    asm volatile(
        "mma.sync.aligned.m16n8k8.row.col.f32.tf32.tf32.f32 "
        "{%0,%1,%2,%3}, {%4,%5,%6,%7}, {%8,%9}, {%0,%1,%2,%3};"
        : "+f"(c[0]), "+f"(c[1]), "+f"(c[2]), "+f"(c[3])
        : "r"(a0), "r"(a1), "r"(a2), "r"(a3), "r"(b0), "r"(b1));
}

// ---------------- init ----------------
__global__ void k_init() {
    int i = blockIdx.x * blockDim.x + threadIdx.x;
    if (i < RPAD_MAX)  g_row2tok[i] = -1;
    if (i < TILES_MAX) g_tile2e[i]  = -1;
    if (i < E_MAX)   { g_count[i] = 0; g_cursor[i] = 0; }
}

// ---------------- router ----------------
__global__ void k_router(const float* __restrict__ x, const float* __restrict__ gw,
                         const float* __restrict__ gb, const int* __restrict__ topk_p,
                         int D, int E) {
    int t = blockIdx.x;
    float acc[E_MAX];
    #pragma unroll
    for (int e = 0; e < E_MAX; e++) acc[e] = 0.f;
    const float* xr = x + (size_t)t * D;
    for (int d = threadIdx.x; d < D; d += blockDim.x) {
        float xv = xr[d];
        for (int e = 0; e < E; e++) acc[e] += xv * gw[(size_t)e * D + d];
    }
    __shared__ float sred[E_MAX][8];
    int lane = threadIdx.x & 31, wid = threadIdx.x >> 5;
    for (int e = 0; e < E; e++) {
        float v = acc[e];
        #pragma unroll
        for (int o = 16; o > 0; o >>= 1) v += __shfl_down_sync(0xffffffffu, v, o);
        if (lane == 0) sred[e][wid] = v;
    }
    __syncthreads();
    if (threadIdx.x == 0) {
        int nw = blockDim.x >> 5;
        float logit[E_MAX], mx = -1e30f;
        for (int e = 0; e < E; e++) {
            float s = gb[e];
            for (int w = 0; w < nw; w++) s += sred[e][w];
            logit[e] = s; mx = fmaxf(mx, s);
        }
        float p[E_MAX], Z = 0.f;
        for (int e = 0; e < E; e++) { p[e] = expf(logit[e] - mx); Z += p[e]; }
        float invZ = 1.f / Z;
        for (int e = 0; e < E; e++) p[e] *= invZ;

        int k = topk_p ? *topk_p : 2;
        if (k > SLOT_MAX) k = SLOT_MAX;
        if (k < 1) k = 1;
        bool used[E_MAX];
        for (int e = 0; e < E; e++) used[e] = false;
        float wsum = 0.f;
        int sels[SLOT_MAX]; float wv[SLOT_MAX];
        for (int s = 0; s < k; s++) {
            int best = 0; float bv = -1.f;
            for (int e = 0; e < E; e++)
                if (!used[e] && p[e] > bv) { bv = p[e]; best = e; }  // strict > => lowest idx on tie
            used[best] = true;
            sels[s] = best; wv[s] = bv; wsum += bv;
            atomicAdd(&g_count[best], 1);
        }
        float inv = 1.f / wsum;
        for (int s = 0; s < k; s++) { g_sel[t*SLOT_MAX+s] = sels[s]; g_wts[t*SLOT_MAX+s] = wv[s]*inv; }
        for (int s = k; s < SLOT_MAX; s++) { g_sel[t*SLOT_MAX+s] = -1; g_wts[t*SLOT_MAX+s] = 0.f; }
    }
}

// ---------------- scan ----------------
__global__ void k_scan(int E) {
    if (threadIdx.x != 0 || blockIdx.x != 0) return;
    int off = 0;
    for (int e = 0; e < E; e++) {
        g_off[e] = off;
        int tiles = (g_count[e] + 127) >> 7;
        for (int i = 0; i < tiles; i++) g_tile2e[(off >> 7) + i] = e;
        off += tiles << 7;
    }
    g_off[E] = off;
}

// ---------------- assign ----------------
__global__ void k_assign(int T) {
    int idx = blockIdx.x * blockDim.x + threadIdx.x;
    if (idx >= T * SLOT_MAX) return;
    int t = idx / SLOT_MAX, s = idx % SLOT_MAX;
    int e = g_sel[t * SLOT_MAX + s];
    if (e < 0) { g_pos[t * SLOT_MAX + s] = -1; return; }
    int pos = atomicAdd(&g_cursor[e], 1);
    int row = g_off[e] + pos;
    g_row2tok[row] = t;
    g_pos[t * SLOT_MAX + s] = row;
}

// ---------------- gather (+ tf32 rna rounding) ----------------
__global__ void k_gather(const float* __restrict__ x, int D) {
    int row = blockIdx.x;
    int tok = g_row2tok[row];
    float4* dst = (float4*)(g_Xg + (size_t)row * D);
    if (tok >= 0) {
        const float4* src = (const float4*)(x + (size_t)tok * D);
        for (int c = threadIdx.x; c < (D >> 2); c += blockDim.x) {
            float4 v = src[c];
            v.x = tf32r(v.x); v.y = tf32r(v.y); v.z = tf32r(v.z); v.w = tf32r(v.w);
            dst[c] = v;
        }
    } else {
        float4 z = make_float4(0.f, 0.f, 0.f, 0.f);
        for (int c = threadIdx.x; c < (D >> 2); c += blockDim.x) dst[c] = z;
    }
}

// ---------------- hybrid GEMM: 128x160 tile = 128x128 tensor + 128x32 SIMT ----------------
// warps 0-3: tensor, one per SMSP, 64x64 each. warps 4-7: SIMT fp32, 32 rows x 32 cols each.
// A: [rows,K] K-contig tf32-pre-rounded; W: [E][K][Ntot] native n-contig raw fp32
// (tensor frags rna-rounded in registers; SIMT uses raw = more accurate);
// bias: [E][Ntot]; C row stride Ntot. act=1 -> SiLU + tf32 rna.
#define BK   16
#define TILE_N 160
#define TSA  20     // A smem row stride
#define TSB  168    // B smem row stride (160 + 8 pad): tensor frag lanes thr*8+grp conflict-free
#define AW   (128 * TSA)     // 2560
#define BW   (BK * TSB)      // 2688
#define SMEM_BYTES ((3 * AW + 3 * BW) * 4)   // 62976

__global__ void __launch_bounds__(256)
k_gemm_hy(const float* __restrict__ Abase, const float* __restrict__ W,
          const float* __restrict__ Ball, float* __restrict__ C,
          int Ntot, int K, int act) {
    int tile_m = blockIdx.y, tile_n = blockIdx.x;
    int e = g_tile2e[tile_m];
    if (e < 0) return;
    int nb = tile_n * TILE_N;

    const float* A = Abase + (size_t)tile_m * 128 * K;
    const float* B = W + (size_t)e * K * Ntot + nb;

    extern __shared__ uint32_t dsm[];
    uint32_t* AsU = dsm;
    uint32_t* BsU = dsm + 3 * AW;
    const float* AsF = (const float*)AsU;
    const float* BsF = (const float*)BsU;

    int tid = threadIdx.x, lane = tid & 31, wid = tid >> 5;
    int grp = lane >> 2, thr = lane & 3;

    // ---- staging roles (all 256 threads) ----
    int ar0 = tid >> 2, ac0 = (tid & 3) * 4;           // A: rows ar0, ar0+64
    uint32_t aS = smem_u32(AsU), bS = smem_u32(BsU);
    uint32_t aOff0 = (uint32_t)((ar0 * TSA + ac0) * 4);
    uint32_t aOff1 = (uint32_t)(((ar0 + 64) * TSA + ac0) * 4);
    const float* aP0 = A + (size_t)ar0 * K + ac0;
    const float* aP1 = A + (size_t)(ar0 + 64) * K + ac0;
    // B: 640 16B segs (16 rows x 40)
    int brow[3], bcw[3], bsz[3]; uint32_t bOff[3];
    #pragma unroll
    for (int i = 0; i < 3; i++) {
        int s = tid + i * 256;
        if (s < 640) {
            brow[i] = s / 40; bcw[i] = (s % 40) * 4;
            bOff[i] = (uint32_t)((brow[i] * TSB + bcw[i]) * 4);
            bsz[i]  = (nb + bcw[i] < Ntot) ? 16 : 0;
        } else { brow[i] = -1; bcw[i] = 0; bOff[i] = 0; bsz[i] = 0; }
    }

    auto stage = [&](int kc, int b) {
        uint32_t ad = aS + (uint32_t)(b * AW * 4);
        uint32_t bd = bS + (uint32_t)(b * BW * 4);
        cp16(ad + aOff0, aP0 + kc * BK);
        cp16(ad + aOff1, aP1 + kc * BK);
        #pragma unroll
        for (int i = 0; i < 3; i++)
            if (brow[i] >= 0)
                cp16z(bd + bOff[i], B + (size_t)(kc * BK + brow[i]) * Ntot + bcw[i], bsz[i]);
    };

    // shared accumulator storage: tensor warps use all 128, SIMT warps use [0,32)
    float acc[128];
    #pragma unroll
    for (int i = 0; i < 128; i++) acc[i] = 0.f;

    int wm  = wid & 1;              // tensor: m half
    int wn2 = (wid >> 1) & 1;       // tensor: n half
    int smB = (wid - 4) * 32;       // simt: m base (valid for wid>=4)
    int sg  = lane >> 2;            // simt row group
    int sc4 = lane & 3;             // simt col group (8 cols)

    int nk = K / BK;
    stage(0, 0); CP_COMMIT();
    if (nk > 1) stage(1, 1);
    CP_COMMIT();

    int buf = 0;
    for (int kc = 0; kc < nk; kc++) {
        CP_WAIT1();
        __syncthreads();
        int sb = buf + 2; if (sb >= 3) sb -= 3;
        if (kc + 2 < nk) stage(kc + 2, sb);
        CP_COMMIT();

        if (wid < 4) {
            // ---------- tensor warp: 64x64 via m16n8k8 tf32 ----------
            const uint32_t* Ab = AsU + buf * AW;
            const uint32_t* Bb = BsU + buf * BW;
            #pragma unroll
            for (int ks = 0; ks < BK; ks += 8) {
                uint32_t af[4][4], bf[8][2];
                #pragma unroll
                for (int mf = 0; mf < 4; mf++) {
                    int m0 = wm * 64 + mf * 16 + grp;
                    af[mf][0] = Ab[(m0    ) * TSA + ks + thr    ];
                    af[mf][1] = Ab[(m0 + 8) * TSA + ks + thr    ];
                    af[mf][2] = Ab[(m0    ) * TSA + ks + thr + 4];
                    af[mf][3] = Ab[(m0 + 8) * TSA + ks + thr + 4];
                }
                #pragma unroll
                for (int nf = 0; nf < 8; nf++) {
                    int n0 = wn2 * 64 + nf * 8 + grp;
                    bf[nf][0] = tf32r_u(Bb[(ks + thr    ) * TSB + n0]);
                    bf[nf][1] = tf32r_u(Bb[(ks + thr + 4) * TSB + n0]);
                }
                #pragma unroll
                for (int mf = 0; mf < 4; mf++)
                    #pragma unroll
                    for (int nf = 0; nf < 8; nf++)
                        mma16n8k8(&acc[(mf * 8 + nf) * 4],
                                  af[mf][0], af[mf][1], af[mf][2], af[mf][3],
                                  bf[nf][0], bf[nf][1]);
            }
        } else {
            // ---------- SIMT warp: 32 rows x 32 cols fp32 FFMA ----------
            const float* AbF = AsF + buf * AW;
            const float* BbF = BsF + buf * BW;
            #pragma unroll
            for (int q = 0; q < 4; q++) {
                float4 av[4];
                #pragma unroll
                for (int r = 0; r < 4; r++)
                    av[r] = *(const float4*)&AbF[(smB + sg + r * 8) * TSA + q * 4];
                #pragma unroll
                for (int kk = 0; kk < 4; kk++) {
                    const float* brow_p = &BbF[(q * 4 + kk) * TSB + 128 + sc4 * 8];
                    float4 b0 = *(const float4*)(brow_p);
                    float4 b1 = *(const float4*)(brow_p + 4);
                    #pragma unroll
                    for (int r = 0; r < 4; r++) {
                        float a = (kk == 0) ? av[r].x : (kk == 1) ? av[r].y
                                : (kk == 2) ? av[r].z : av[r].w;
                        acc[r * 8 + 0] = fmaf(a, b0.x, acc[r * 8 + 0]);
                        acc[r * 8 + 1] = fmaf(a, b0.y, acc[r * 8 + 1]);
                        acc[r * 8 + 2] = fmaf(a, b0.z, acc[r * 8 + 2]);
                        acc[r * 8 + 3] = fmaf(a, b0.w, acc[r * 8 + 3]);
                        acc[r * 8 + 4] = fmaf(a, b1.x, acc[r * 8 + 4]);
                        acc[r * 8 + 5] = fmaf(a, b1.y, acc[r * 8 + 5]);
                        acc[r * 8 + 6] = fmaf(a, b1.z, acc[r * 8 + 6]);
                        acc[r * 8 + 7] = fmaf(a, b1.w, acc[r * 8 + 7]);
                    }
                }
            }
        }
        buf = buf + 1; if (buf == 3) buf = 0;
    }

    // ---------------- epilogue ----------------
    const float* bias = Ball + (size_t)e * Ntot;
    float* Crow = C + (size_t)tile_m * 128 * Ntot;

    if (wid < 4) {
        #pragma unroll
        for (int mf = 0; mf < 4; mf++) {
            #pragma unroll
            for (int nf = 0; nf < 8; nf++) {
                int row = wm * 64 + mf * 16 + grp;
                int gcol = nb + wn2 * 64 + nf * 8 + thr * 2;
                if (gcol < Ntot) {
                    float b0 = bias[gcol], b1 = bias[gcol + 1];
                    float* a4 = &acc[(mf * 8 + nf) * 4];
                    float v00 = a4[0] + b0, v01 = a4[1] + b1;
                    float v10 = a4[2] + b0, v11 = a4[3] + b1;
                    if (act) {
                        v00 = tf32r(v00 / (1.f + __expf(-v00)));
                        v01 = tf32r(v01 / (1.f + __expf(-v01)));
                        v10 = tf32r(v10 / (1.f + __expf(-v10)));
                        v11 = tf32r(v11 / (1.f + __expf(-v11)));
                    }
                    *(float2*)(Crow + (size_t)row * Ntot + gcol)       = make_float2(v00, v01);
                    *(float2*)(Crow + (size_t)(row + 8) * Ntot + gcol) = make_float2(v10, v11);
                }
            }
        }
    } else {
        int gc = nb + 128 + sc4 * 8;
        if (gc < Ntot) {
            #pragma unroll
            for (int r = 0; r < 4; r++) {
                int row = smB + sg + r * 8;
                #pragma unroll
                for (int h = 0; h < 2; h++) {
                    int c0 = gc + h * 4;
                    float4 bv = *(const float4*)&bias[c0];
                    float v0 = acc[r * 8 + h * 4 + 0] + bv.x;
                    float v1 = acc[r * 8 + h * 4 + 1] + bv.y;
                    float v2 = acc[r * 8 + h * 4 + 2] + bv.z;
                    float v3 = acc[r * 8 + h * 4 + 3] + bv.w;
                    if (act) {
                        v0 = tf32r(v0 / (1.f + __expf(-v0)));
                        v1 = tf32r(v1 / (1.f + __expf(-v1)));
                        v2 = tf32r(v2 / (1.f + __expf(-v2)));
                        v3 = tf32r(v3 / (1.f + __expf(-v3)));
                    }
                    float4 o = make_float4(v0, v1, v2, v3);
                    *(float4*)(Crow + (size_t)row * Ntot + c0) = o;
                }
            }
        }
    }
}

// ---------------- combine ----------------
__global__ void k_combine(float* __restrict__ out, int D) {
    int t = blockIdx.x;
    int rows[SLOT_MAX]; float ws[SLOT_MAX];
    #pragma unroll
    for (int s = 0; s < SLOT_MAX; s++) { rows[s] = g_pos[t*SLOT_MAX+s]; ws[s] = g_wts[t*SLOT_MAX+s]; }
    float4* dst = (float4*)(out + (size_t)t * D);
    for (int c = threadIdx.x; c < (D >> 2); c += blockDim.x) {
        float4 a = make_float4(0.f, 0.f, 0.f, 0.f);
        #pragma unroll
        for (int s = 0; s < SLOT_MAX; s++) {
            if (rows[s] < 0) continue;
            const float4 v = ((const float4*)(g_O + (size_t)rows[s] * D))[c];
            a.x = fmaf(ws[s], v.x, a.x); a.y = fmaf(ws[s], v.y, a.y);
            a.z = fmaf(ws[s], v.z, a.z); a.w = fmaf(ws[s], v.w, a.w);
        }
        dst[c] = a;
    }
}

// ---------------- launch ----------------
extern "C" void kernel_launch(void* const* d_in, const int* in_sizes, int n_in,
                              void* d_out, int out_size) {
    const float* x    = (const float*)d_in[0];
    const float* gw   = (const float*)d_in[1];
    const float* gb   = (const float*)d_in[2];
    const float* w1   = (const float*)d_in[3];
    const float* b1   = (const float*)d_in[4];
    const float* w2   = (const float*)d_in[5];
    const float* b2   = (const float*)d_in[6];
    const int*   topk = (n_in > 7) ? (const int*)d_in[7] : nullptr;
    float* out = (float*)d_out;

    const int E = in_sizes[2];
    const int D = in_sizes[1] / E;
    const int F = in_sizes[4] / E;
    const int T = in_sizes[0] / D;

    float *Xg = nullptr, *H = nullptr, *O = nullptr;
    cudaGetSymbolAddress((void**)&Xg, g_Xg);
    cudaGetSymbolAddress((void**)&H,  g_H);
    cudaGetSymbolAddress((void**)&O,  g_O);

    cudaFuncSetAttribute(k_gemm_hy, cudaFuncAttributeMaxDynamicSharedMemorySize, SMEM_BYTES);

    k_init<<<(RPAD_MAX + 255) / 256, 256>>>();
    k_router<<<T, 256>>>(x, gw, gb, topk, D, E);
    k_scan<<<1, 32>>>(E);
    k_assign<<<(T * SLOT_MAX + 255) / 256, 256>>>(T);
    k_gather<<<RPAD_MAX, 256>>>(x, D);

    int nt1 = (F + TILE_N - 1) / TILE_N;   // 26
    int nt2 = (D + TILE_N - 1) / TILE_N;   // 7
    k_gemm_hy<<<dim3(nt1, TILES_MAX), 256, SMEM_BYTES>>>(Xg, w1, b1, H, F, D, 1);
    k_gemm_hy<<<dim3(nt2, TILES_MAX), 256, SMEM_BYTES>>>(H, w2, b2, O, D, F, 0);

    k_combine<<<T, 256>>>(out, D);
}

// round 9
// speedup vs baseline: 1.1931x; 1.1931x over previous
#include <cuda_runtime.h>
#include <cuda_bf16.h>
#include <math.h>
#include <stdint.h>

// ---------------- problem-size maxima (fixed instance: T=4096,D=1024,F=4096,E=8,k=2)
#define T_MAX    4096
#define E_MAX    8
#define SLOT_MAX 2
#define D_MAX    1024
#define F_MAX    4096
#define RPAD_MAX (T_MAX * SLOT_MAX + E_MAX * 128)   // 9216
#define TILES_MAX (RPAD_MAX / 128)                  // 72

// ---------------- device scratch (static: no allocation anywhere)
__device__ float g_Xg [(size_t)RPAD_MAX * D_MAX];   // gathered tokens (tf32-rounded)
__device__ float g_H  [(size_t)RPAD_MAX * F_MAX];   // hidden (tf32-rounded)
__device__ float g_O  [(size_t)RPAD_MAX * D_MAX];   // expert outputs (fp32)
__device__ int   g_sel [T_MAX * SLOT_MAX];
__device__ float g_wts [T_MAX * SLOT_MAX];
__device__ int   g_pos [T_MAX * SLOT_MAX];
__device__ int   g_count [E_MAX];
__device__ int   g_cursor[E_MAX];
__device__ int   g_off   [E_MAX + 1];
__device__ int   g_tile2e[TILES_MAX];
__device__ int   g_row2tok[RPAD_MAX];

// ---------------- helpers ----------------
__device__ __forceinline__ float tf32r(float x) {
    uint32_t u;
    asm("cvt.rna.tf32.f32 %0, %1;" : "=r"(u) : "f"(x));
    return __uint_as_float(u);
}
__device__ __forceinline__ uint32_t tf32r_u(uint32_t x) {
    uint32_t u;
    asm("cvt.rna.tf32.f32 %0, %1;" : "=r"(u) : "f"(__uint_as_float(x)));
    return u;
}
__device__ __forceinline__ uint32_t smem_u32(const void* p) {
    uint32_t a;
    asm("{ .reg .u64 t; cvta.to.shared.u64 t, %1; cvt.u32.u64 %0, t; }" : "=r"(a) : "l"(p));
    return a;
}
__device__ __forceinline__ void cp16(uint32_t dst, const void* src) {
    asm volatile("cp.async.cg.shared.global [%0], [%1], 16;" :: "r"(dst), "l"(src));
}
#define CP_COMMIT() asm volatile("cp.async.commit_group;" ::: "memory")
#define CP_WAIT1()  asm volatile("cp.async.wait_group 1;" ::: "memory")

__device__ __forceinline__ void mma16n8k8(float* c,
                                          uint32_t a0, uint32_t a1, uint32_t a2, uint32_t a3,
                                          uint32_t b0, uint32_t b1) {
    asm volatile(
        "mma.sync.aligned.m16n8k8.row.col.f32.tf32.tf32.f32 "
        "{%0,%1,%2,%3}, {%4,%5,%6,%7}, {%8,%9}, {%0,%1,%2,%3};"
        : "+f"(c[0]), "+f"(c[1]), "+f"(c[2]), "+f"(c[3])
        : "r"(a0), "r"(a1), "r"(a2), "r"(a3), "r"(b0), "r"(b1));
}

// ---------------- init ----------------
__global__ void k_init() {
    int i = blockIdx.x * blockDim.x + threadIdx.x;
    if (i < RPAD_MAX)  g_row2tok[i] = -1;
    if (i < TILES_MAX) g_tile2e[i]  = -1;
    if (i < E_MAX)   { g_count[i] = 0; g_cursor[i] = 0; }
}

// ---------------- router ----------------
__global__ void k_router(const float* __restrict__ x, const float* __restrict__ gw,
                         const float* __restrict__ gb, const int* __restrict__ topk_p,
                         int D, int E) {
    int t = blockIdx.x;
    float acc[E_MAX];
    #pragma unroll
    for (int e = 0; e < E_MAX; e++) acc[e] = 0.f;
    const float* xr = x + (size_t)t * D;
    for (int d = threadIdx.x; d < D; d += blockDim.x) {
        float xv = xr[d];
        for (int e = 0; e < E; e++) acc[e] += xv * gw[(size_t)e * D + d];
    }
    __shared__ float sred[E_MAX][8];
    int lane = threadIdx.x & 31, wid = threadIdx.x >> 5;
    for (int e = 0; e < E; e++) {
        float v = acc[e];
        #pragma unroll
        for (int o = 16; o > 0; o >>= 1) v += __shfl_down_sync(0xffffffffu, v, o);
        if (lane == 0) sred[e][wid] = v;
    }
    __syncthreads();
    if (threadIdx.x == 0) {
        int nw = blockDim.x >> 5;
        float logit[E_MAX], mx = -1e30f;
        for (int e = 0; e < E; e++) {
            float s = gb[e];
            for (int w = 0; w < nw; w++) s += sred[e][w];
            logit[e] = s; mx = fmaxf(mx, s);
        }
        float p[E_MAX], Z = 0.f;
        for (int e = 0; e < E; e++) { p[e] = expf(logit[e] - mx); Z += p[e]; }
        float invZ = 1.f / Z;
        for (int e = 0; e < E; e++) p[e] *= invZ;

        int k = topk_p ? *topk_p : 2;
        if (k > SLOT_MAX) k = SLOT_MAX;
        if (k < 1) k = 1;
        bool used[E_MAX];
        for (int e = 0; e < E; e++) used[e] = false;
        float wsum = 0.f;
        int sels[SLOT_MAX]; float wv[SLOT_MAX];
        for (int s = 0; s < k; s++) {
            int best = 0; float bv = -1.f;
            for (int e = 0; e < E; e++)
                if (!used[e] && p[e] > bv) { bv = p[e]; best = e; }  // strict > => lowest idx on tie
            used[best] = true;
            sels[s] = best; wv[s] = bv; wsum += bv;
            atomicAdd(&g_count[best], 1);
        }
        float inv = 1.f / wsum;
        for (int s = 0; s < k; s++) { g_sel[t*SLOT_MAX+s] = sels[s]; g_wts[t*SLOT_MAX+s] = wv[s]*inv; }
        for (int s = k; s < SLOT_MAX; s++) { g_sel[t*SLOT_MAX+s] = -1; g_wts[t*SLOT_MAX+s] = 0.f; }
    }
}

// ---------------- scan ----------------
__global__ void k_scan(int E) {
    if (threadIdx.x != 0 || blockIdx.x != 0) return;
    int off = 0;
    for (int e = 0; e < E; e++) {
        g_off[e] = off;
        int tiles = (g_count[e] + 127) >> 7;
        for (int i = 0; i < tiles; i++) g_tile2e[(off >> 7) + i] = e;
        off += tiles << 7;
    }
    g_off[E] = off;
}

// ---------------- assign ----------------
__global__ void k_assign(int T) {
    int idx = blockIdx.x * blockDim.x + threadIdx.x;
    if (idx >= T * SLOT_MAX) return;
    int t = idx / SLOT_MAX, s = idx % SLOT_MAX;
    int e = g_sel[t * SLOT_MAX + s];
    if (e < 0) { g_pos[t * SLOT_MAX + s] = -1; return; }
    int pos = atomicAdd(&g_cursor[e], 1);
    int row = g_off[e] + pos;
    g_row2tok[row] = t;
    g_pos[t * SLOT_MAX + s] = row;
}

// ---------------- gather (+ tf32 rna rounding) ----------------
__global__ void k_gather(const float* __restrict__ x, int D) {
    int row = blockIdx.x;
    int tok = g_row2tok[row];
    float4* dst = (float4*)(g_Xg + (size_t)row * D);
    if (tok >= 0) {
        const float4* src = (const float4*)(x + (size_t)tok * D);
        for (int c = threadIdx.x; c < (D >> 2); c += blockDim.x) {
            float4 v = src[c];
            v.x = tf32r(v.x); v.y = tf32r(v.y); v.z = tf32r(v.z); v.w = tf32r(v.w);
            dst[c] = v;
        }
    } else {
        float4 z = make_float4(0.f, 0.f, 0.f, 0.f);
        for (int c = threadIdx.x; c < (D >> 2); c += blockDim.x) dst[c] = z;
    }
}

// ---------------- mixed-role GEMM ----------------
// tile_n < ntT  : tensor role — R6 path (mma.sync tf32, cp.async 3-buf pipeline)
// tile_n >= ntT : SIMT role  — fp32 FFMA path (R2 design), mops up trailing columns
// C[128x128 tile] = act(A @ W[e] + bias[e])
// A: [rows,K] K-contig tf32-pre-rounded; W: [E][K][Ntot] native n-contig;
// bias: [E][Ntot]; C row stride Ntot. act=1 -> SiLU + tf32 rna.
#define BK  16
#define TSA 20     // A smem row stride: frag addr grp*20+thr -> all 32 banks
#define TSB 136    // B smem row stride: frag addr thr*136+grp ≡ thr*8+grp -> all 32 banks
#define AW  (128 * TSA)     // 2560 uints per A buffer
#define BW  (BK * TSB)      // 2176 uints per B buffer
#define SM_UINTS (3 * AW + 3 * BW)   // 14208 uints = 56832 B

__global__ void __launch_bounds__(256, 2)
k_gemm_mix(const float* __restrict__ Abase, const float* __restrict__ W,
           const float* __restrict__ Ball, float* __restrict__ C,
           int Ntot, int K, int act, int ntT) {
    int tile_m = blockIdx.y, tile_n = blockIdx.x;
    int e = g_tile2e[tile_m];
    if (e < 0) return;

    __shared__ uint32_t smu[SM_UINTS];

    const float* A = Abase + (size_t)tile_m * 128 * K;
    const float* B = W + (size_t)e * K * Ntot + (size_t)tile_n * 128;   // [k][n], n-contig
    const float* bias = Ball + (size_t)e * Ntot + (size_t)tile_n * 128;
    float*       Cb   = C + (size_t)tile_m * 128 * Ntot + (size_t)tile_n * 128;

    int tid = threadIdx.x, lane = tid & 31, wid = tid >> 5;

    if (tile_n < ntT) {
        // ================= TENSOR ROLE (R6 path, unchanged) =================
        uint32_t* As = smu;                 // [3][128][TSA]
        uint32_t* Bs = smu + 3 * AW;        // [3][BK][TSB]
        int wm = wid & 1, wn = wid >> 1;    // warp tile 64(m) x 32(n)
        int grp = lane >> 2, thr = lane & 3;

        int ar0 = tid >> 2, ac0 = (tid & 3) * 4;
        int ar1 = (ar0 + 64);
        int br0 = tid >> 5, bc0 = (tid & 31) * 4;   // 16 rows x 32 segs = 512 segs; 2 rows/thread-pass
        uint32_t aS = smem_u32(As), bS = smem_u32(Bs);
        uint32_t aOff0 = (uint32_t)((ar0 * TSA + ac0) * 4);
        uint32_t aOff1 = (uint32_t)((ar1 * TSA + ac0) * 4);
        uint32_t bOff0 = (uint32_t)((br0 * TSB + bc0) * 4);
        uint32_t bOff1 = (uint32_t)(((br0 + 8) * TSB + bc0) * 4);
        const float* aP0 = A + (size_t)ar0 * K + ac0;
        const float* aP1 = A + (size_t)ar1 * K + ac0;
        const float* bP0 = B + (size_t)br0 * Ntot + bc0;
        const float* bP1 = B + (size_t)(br0 + 8) * Ntot + bc0;

        float acc[4][4][4];
        #pragma unroll
        for (int mf = 0; mf < 4; mf++)
            #pragma unroll
            for (int nf = 0; nf < 4; nf++)
                #pragma unroll
                for (int c = 0; c < 4; c++) acc[mf][nf][c] = 0.f;

        int nk = K / BK;
        auto stage = [&](int kc, int b) {
            uint32_t ad = aS + (uint32_t)(b * AW * 4);
            uint32_t bd = bS + (uint32_t)(b * BW * 4);
            cp16(ad + aOff0, aP0 + kc * BK);
            cp16(ad + aOff1, aP1 + kc * BK);
            const size_t bk = (size_t)kc * BK * Ntot;
            cp16(bd + bOff0, bP0 + bk);
            cp16(bd + bOff1, bP1 + bk);
        };

        stage(0, 0); CP_COMMIT();
        if (nk > 1) stage(1, 1);
        CP_COMMIT();

        int buf = 0;
        for (int kc = 0; kc < nk; kc++) {
            CP_WAIT1();
            __syncthreads();
            int sb = buf + 2; if (sb >= 3) sb -= 3;
            if (kc + 2 < nk) stage(kc + 2, sb);
            CP_COMMIT();

            const uint32_t* Ab = As + buf * AW;
            const uint32_t* Bb = Bs + buf * BW;
            #pragma unroll
            for (int ks = 0; ks < BK; ks += 8) {
                uint32_t af[4][4], bf[4][2];
                #pragma unroll
                for (int mf = 0; mf < 4; mf++) {
                    int m0 = wm * 64 + mf * 16 + grp;
                    af[mf][0] = Ab[(m0    ) * TSA + ks + thr    ];
                    af[mf][1] = Ab[(m0 + 8) * TSA + ks + thr    ];
                    af[mf][2] = Ab[(m0    ) * TSA + ks + thr + 4];
                    af[mf][3] = Ab[(m0 + 8) * TSA + ks + thr + 4];
                }
                #pragma unroll
                for (int nf = 0; nf < 4; nf++) {
                    int n0 = wn * 32 + nf * 8 + grp;
                    bf[nf][0] = tf32r_u(Bb[(ks + thr    ) * TSB + n0]);
                    bf[nf][1] = tf32r_u(Bb[(ks + thr + 4) * TSB + n0]);
                }
                #pragma unroll
                for (int mf = 0; mf < 4; mf++)
                    #pragma unroll
                    for (int nf = 0; nf < 4; nf++)
                        mma16n8k8(&acc[mf][nf][0], af[mf][0], af[mf][1], af[mf][2], af[mf][3],
                                  bf[nf][0], bf[nf][1]);
            }
            buf = buf + 1; if (buf == 3) buf = 0;
        }

        #pragma unroll
        for (int mf = 0; mf < 4; mf++) {
            #pragma unroll
            for (int nf = 0; nf < 4; nf++) {
                int row = wm * 64 + mf * 16 + grp;
                int col = wn * 32 + nf * 8 + thr * 2;
                float b0 = bias[col], b1 = bias[col + 1];
                float v00 = acc[mf][nf][0] + b0, v01 = acc[mf][nf][1] + b1;
                float v10 = acc[mf][nf][2] + b0, v11 = acc[mf][nf][3] + b1;
                if (act) {
                    v00 = tf32r(v00 / (1.f + __expf(-v00)));
                    v01 = tf32r(v01 / (1.f + __expf(-v01)));
                    v10 = tf32r(v10 / (1.f + __expf(-v10)));
                    v11 = tf32r(v11 / (1.f + __expf(-v11)));
                }
                *(float2*)(Cb + (size_t)row * Ntot + col)       = make_float2(v00, v01);
                *(float2*)(Cb + (size_t)(row + 8) * Ntot + col) = make_float2(v10, v11);
            }
        }
    } else {
        // ================= SIMT ROLE (fp32 FFMA, R2 design) =================
        float* As2 = (float*)smu;             // [16][132]
        float* Bs2 = (float*)smu + 16 * 132;  // [16][128]

        int tx = tid & 15, ty = tid >> 4;
        float acc[8][8];
        #pragma unroll
        for (int i = 0; i < 8; i++)
            #pragma unroll
            for (int j = 0; j < 8; j++) acc[i][j] = 0.f;

        for (int k0 = 0; k0 < K; k0 += 16) {
            #pragma unroll
            for (int l = 0; l < 2; l++) {
                int q = tid + l * 256;
                int ar = q >> 2, ak = (q & 3) << 2;
                float4 av = *(const float4*)(A + (size_t)ar * K + k0 + ak);
                As2[(ak + 0) * 132 + ar] = av.x;
                As2[(ak + 1) * 132 + ar] = av.y;
                As2[(ak + 2) * 132 + ar] = av.z;
                As2[(ak + 3) * 132 + ar] = av.w;
                int bk = q >> 5, bc = (q & 31) << 2;
                *(float4*)&Bs2[bk * 128 + bc] = *(const float4*)(B + (size_t)(k0 + bk) * Ntot + bc);
            }
            __syncthreads();
            #pragma unroll
            for (int kk = 0; kk < 16; kk++) {
                float ra[8], rb[8];
                #pragma unroll
                for (int i = 0; i < 8; i++) ra[i] = As2[kk * 132 + ty * 8 + i];
                #pragma unroll
                for (int j = 0; j < 8; j++) rb[j] = Bs2[kk * 128 + tx * 8 + j];
                #pragma unroll
                for (int i = 0; i < 8; i++)
                    #pragma unroll
                    for (int j = 0; j < 8; j++) acc[i][j] = fmaf(ra[i], rb[j], acc[i][j]);
            }
            __syncthreads();
        }
        #pragma unroll
        for (int i = 0; i < 8; i++) {
            int m = ty * 8 + i;
            #pragma unroll
            for (int j = 0; j < 8; j++) {
                int n = tx * 8 + j;
                float v = acc[i][j] + bias[n];
                if (act) v = tf32r(v / (1.f + __expf(-v)));   // keep H tf32-exact
                Cb[(size_t)m * Ntot + n] = v;
            }
        }
    }
}

// ---------------- combine ----------------
__global__ void k_combine(float* __restrict__ out, int D) {
    int t = blockIdx.x;
    int rows[SLOT_MAX]; float ws[SLOT_MAX];
    #pragma unroll
    for (int s = 0; s < SLOT_MAX; s++) { rows[s] = g_pos[t*SLOT_MAX+s]; ws[s] = g_wts[t*SLOT_MAX+s]; }
    float4* dst = (float4*)(out + (size_t)t * D);
    for (int c = threadIdx.x; c < (D >> 2); c += blockDim.x) {
        float4 a = make_float4(0.f, 0.f, 0.f, 0.f);
        #pragma unroll
        for (int s = 0; s < SLOT_MAX; s++) {
            if (rows[s] < 0) continue;
            const float4 v = ((const float4*)(g_O + (size_t)rows[s] * D))[c];
            a.x = fmaf(ws[s], v.x, a.x); a.y = fmaf(ws[s], v.y, a.y);
            a.z = fmaf(ws[s], v.z, a.z); a.w = fmaf(ws[s], v.w, a.w);
        }
        dst[c] = a;
    }
}

// ---------------- launch ----------------
extern "C" void kernel_launch(void* const* d_in, const int* in_sizes, int n_in,
                              void* d_out, int out_size) {
    const float* x    = (const float*)d_in[0];
    const float* gw   = (const float*)d_in[1];
    const float* gb   = (const float*)d_in[2];
    const float* w1   = (const float*)d_in[3];
    const float* b1   = (const float*)d_in[4];
    const float* w2   = (const float*)d_in[5];
    const float* b2   = (const float*)d_in[6];
    const int*   topk = (n_in > 7) ? (const int*)d_in[7] : nullptr;
    float* out = (float*)d_out;

    const int E = in_sizes[2];
    const int D = in_sizes[1] / E;
    const int F = in_sizes[4] / E;
    const int T = in_sizes[0] / D;

    float *Xg = nullptr, *H = nullptr, *O = nullptr;
    cudaGetSymbolAddress((void**)&Xg, g_Xg);
    cudaGetSymbolAddress((void**)&H,  g_H);
    cudaGetSymbolAddress((void**)&O,  g_O);

    k_init<<<(RPAD_MAX + 255) / 256, 256>>>();
    k_router<<<T, 256>>>(x, gw, gb, topk, D, E);
    k_scan<<<1, 32>>>(E);
    k_assign<<<(T * SLOT_MAX + 255) / 256, 256>>>(T);
    k_gather<<<RPAD_MAX, 256>>>(x, D);

    // role split: trailing N-tiles go to the SIMT (fma-pipe) role
    int nt1 = F / 128;                         // 32
    int ntT1 = nt1 - 6;                        // 26 tensor + 6 simt (~19%)
    int nt2 = D / 128;                         // 8
    int ntT2 = nt2 - 1;                        // 7 tensor + 1 simt (12.5%)

    k_gemm_mix<<<dim3(nt1, TILES_MAX), 256>>>(Xg, w1, b1, H, F, D, 1, ntT1);
    k_gemm_mix<<<dim3(nt2, TILES_MAX), 256>>>(H, w2, b2, O, D, F, 0, ntT2);

    k_combine<<<T, 256>>>(out, D);
}

// round 11
// speedup vs baseline: 2.8586x; 2.3958x over previous
#include <cuda_runtime.h>
#include <cuda_fp16.h>
#include <math.h>
#include <stdint.h>

// ---------------- problem-size maxima (fixed instance: T=4096,D=1024,F=4096,E=8,k=2)
#define T_MAX    4096
#define E_MAX    8
#define SLOT_MAX 2
#define D_MAX    1024
#define F_MAX    4096
#define RPAD_MAX (T_MAX * SLOT_MAX + E_MAX * 128)   // 9216
#define TILES_MAX (RPAD_MAX / 128)                  // 72

// ---------------- device scratch (static: no allocation anywhere)
__device__ __half g_Xh [(size_t)RPAD_MAX * D_MAX];          // gathered tokens, fp16
__device__ __half g_Hh [(size_t)RPAD_MAX * F_MAX];          // hidden, fp16
__device__ float  g_O  [(size_t)RPAD_MAX * D_MAX];          // expert outputs, fp32
__device__ __half g_W1h[(size_t)E_MAX * F_MAX * D_MAX];     // w1^T [E][F][D] fp16
__device__ __half g_W2h[(size_t)E_MAX * D_MAX * F_MAX];     // w2^T [E][D][F] fp16
__device__ int    g_sel [T_MAX * SLOT_MAX];
__device__ float  g_wts [T_MAX * SLOT_MAX];
__device__ int    g_pos [T_MAX * SLOT_MAX];
__device__ int    g_count [E_MAX];
__device__ int    g_cursor[E_MAX];
__device__ int    g_off   [E_MAX + 1];
__device__ int    g_tile2e[TILES_MAX];
__device__ int    g_row2tok[RPAD_MAX];

// ---------------- helpers ----------------
__device__ __forceinline__ uint32_t smem_u32(const void* p) {
    uint32_t a;
    asm("{ .reg .u64 t; cvta.to.shared.u64 t, %1; cvt.u32.u64 %0, t; }" : "=r"(a) : "l"(p));
    return a;
}
__device__ __forceinline__ void cp16(uint32_t dst, const void* src) {
    asm volatile("cp.async.cg.shared.global [%0], [%1], 16;" :: "r"(dst), "l"(src));
}
#define CP_COMMIT() asm volatile("cp.async.commit_group;" ::: "memory")
#define CP_WAIT1()  asm volatile("cp.async.wait_group 1;" ::: "memory")

// fp16 tensor op, baseline target (compiles for compute_103): K=16 per instruction
__device__ __forceinline__ void mma16n8k16(float* c,
                                           uint32_t a0, uint32_t a1, uint32_t a2, uint32_t a3,
                                           uint32_t b0, uint32_t b1) {
    asm volatile(
        "mma.sync.aligned.m16n8k16.row.col.f32.f16.f16.f32 "
        "{%0,%1,%2,%3}, {%4,%5,%6,%7}, {%8,%9}, {%0,%1,%2,%3};"
        : "+f"(c[0]), "+f"(c[1]), "+f"(c[2]), "+f"(c[3])
        : "r"(a0), "r"(a1), "r"(a2), "r"(a3), "r"(b0), "r"(b1));
}

// ---------------- init ----------------
__global__ void k_init() {
    int i = blockIdx.x * blockDim.x + threadIdx.x;
    if (i < RPAD_MAX)  g_row2tok[i] = -1;
    if (i < TILES_MAX) g_tile2e[i]  = -1;
    if (i < E_MAX)   { g_count[i] = 0; g_cursor[i] = 0; }
}

// ---------------- router ----------------
__global__ void k_router(const float* __restrict__ x, const float* __restrict__ gw,
                         const float* __restrict__ gb, const int* __restrict__ topk_p,
                         int D, int E) {
    int t = blockIdx.x;
    float acc[E_MAX];
    #pragma unroll
    for (int e = 0; e < E_MAX; e++) acc[e] = 0.f;
    const float* xr = x + (size_t)t * D;
    for (int d = threadIdx.x; d < D; d += blockDim.x) {
        float xv = xr[d];
        for (int e = 0; e < E; e++) acc[e] += xv * gw[(size_t)e * D + d];
    }
    __shared__ float sred[E_MAX][8];
    int lane = threadIdx.x & 31, wid = threadIdx.x >> 5;
    for (int e = 0; e < E; e++) {
        float v = acc[e];
        #pragma unroll
        for (int o = 16; o > 0; o >>= 1) v += __shfl_down_sync(0xffffffffu, v, o);
        if (lane == 0) sred[e][wid] = v;
    }
    __syncthreads();
    if (threadIdx.x == 0) {
        int nw = blockDim.x >> 5;
        float logit[E_MAX], mx = -1e30f;
        for (int e = 0; e < E; e++) {
            float s = gb[e];
            for (int w = 0; w < nw; w++) s += sred[e][w];
            logit[e] = s; mx = fmaxf(mx, s);
        }
        float p[E_MAX], Z = 0.f;
        for (int e = 0; e < E; e++) { p[e] = expf(logit[e] - mx); Z += p[e]; }
        float invZ = 1.f / Z;
        for (int e = 0; e < E; e++) p[e] *= invZ;

        int k = topk_p ? *topk_p : 2;
        if (k > SLOT_MAX) k = SLOT_MAX;
        if (k < 1) k = 1;
        bool used[E_MAX];
        for (int e = 0; e < E; e++) used[e] = false;
        float wsum = 0.f;
        int sels[SLOT_MAX]; float wv[SLOT_MAX];
        for (int s = 0; s < k; s++) {
            int best = 0; float bv = -1.f;
            for (int e = 0; e < E; e++)
                if (!used[e] && p[e] > bv) { bv = p[e]; best = e; }  // strict > => lowest idx on tie
            used[best] = true;
            sels[s] = best; wv[s] = bv; wsum += bv;
            atomicAdd(&g_count[best], 1);
        }
        float inv = 1.f / wsum;
        for (int s = 0; s < k; s++) { g_sel[t*SLOT_MAX+s] = sels[s]; g_wts[t*SLOT_MAX+s] = wv[s]*inv; }
        for (int s = k; s < SLOT_MAX; s++) { g_sel[t*SLOT_MAX+s] = -1; g_wts[t*SLOT_MAX+s] = 0.f; }
    }
}

// ---------------- scan ----------------
__global__ void k_scan(int E) {
    if (threadIdx.x != 0 || blockIdx.x != 0) return;
    int off = 0;
    for (int e = 0; e < E; e++) {
        g_off[e] = off;
        int tiles = (g_count[e] + 127) >> 7;
        for (int i = 0; i < tiles; i++) g_tile2e[(off >> 7) + i] = e;
        off += tiles << 7;
    }
    g_off[E] = off;
}

// ---------------- assign ----------------
__global__ void k_assign(int T) {
    int idx = blockIdx.x * blockDim.x + threadIdx.x;
    if (idx >= T * SLOT_MAX) return;
    int t = idx / SLOT_MAX, s = idx % SLOT_MAX;
    int e = g_sel[t * SLOT_MAX + s];
    if (e < 0) { g_pos[t * SLOT_MAX + s] = -1; return; }
    int pos = atomicAdd(&g_cursor[e], 1);
    int row = g_off[e] + pos;
    g_row2tok[row] = t;
    g_pos[t * SLOT_MAX + s] = row;
}

// ---------------- gather: fp32 tokens -> fp16 rows (zeros for pad) ----------------
__global__ void k_gather(const float* __restrict__ x, int D) {
    int row = blockIdx.x;
    int tok = g_row2tok[row];
    __half2* dst = (__half2*)(g_Xh + (size_t)row * D);
    if (tok >= 0) {
        const float2* src = (const float2*)(x + (size_t)tok * D);
        for (int c = threadIdx.x; c < (D >> 1); c += blockDim.x) {
            float2 v = src[c];
            dst[c] = __floats2half2_rn(v.x, v.y);
        }
    } else {
        __half2 z = __floats2half2_rn(0.f, 0.f);
        for (int c = threadIdx.x; c < (D >> 1); c += blockDim.x) dst[c] = z;
    }
}

// ---------------- weight convert+transpose: fp32 [E][K][N] -> fp16 [E][N][K] ----------------
__global__ void k_wconv(const float* __restrict__ W, __half* __restrict__ Wt, int K, int N) {
    __shared__ float t[32][33];
    int e = blockIdx.z;
    const float* We = W + (size_t)e * K * N;
    __half* Wte = Wt + (size_t)e * N * K;
    int n0 = blockIdx.x * 32, k0 = blockIdx.y * 32;
    #pragma unroll
    for (int i = 0; i < 32; i += 8) {
        int k = k0 + threadIdx.y + i;
        t[threadIdx.y + i][threadIdx.x] = We[(size_t)k * N + n0 + threadIdx.x];
    }
    __syncthreads();
    #pragma unroll
    for (int i = 0; i < 32; i += 8) {
        int n = n0 + threadIdx.y + i;
        Wte[(size_t)n * K + k0 + threadIdx.x] = __float2half_rn(t[threadIdx.x][threadIdx.y + i]);
    }
}

// ---------------- fp16 tensor GEMM: 128x128 tile, m16n8k16, cp.async 3-buf ----------------
// A: [rows][K] halfs k-contig; Wt: [E][Ntot][K] halfs k-contig; bias: [E][Ntot] fp32;
// act=1 -> silu, store fp16 (H);  act=0 -> store fp32 (O). C row stride Ntot.
#define BK  32                  // halfs per chunk = 64B rows
#define TS2 20                  // smem row stride in b32 (16 data + 4 pad): lanes g*20+t -> 32 banks
#define BUF32 (128 * TS2)       // b32 per buffer (A or B) = 2560 -> 10240 B
#define GSMEM (6 * BUF32 * 4)   // 3 A + 3 B buffers = 61440 B

__global__ void __launch_bounds__(256, 2)
k_gemm_h(const __half* __restrict__ Abase, const __half* __restrict__ Wt,
         const float* __restrict__ Ball, void* __restrict__ Cout,
         int Ntot, int K, int act) {
    int tile_m = blockIdx.y, tile_n = blockIdx.x;
    int e = g_tile2e[tile_m];
    if (e < 0) return;

    extern __shared__ uint32_t smu[];
    uint32_t* As = smu;                  // [3][128][TS2]
    uint32_t* Bs = smu + 3 * BUF32;      // [3][128][TS2]

    const __half* A = Abase + (size_t)tile_m * 128 * K;
    const __half* B = Wt + (size_t)e * Ntot * K + (size_t)tile_n * 128 * K;  // [n][k]

    int tid = threadIdx.x, lane = tid & 31, wid = tid >> 5;
    int wm = wid & 1, wn = wid >> 1;     // warp tile 64(m) x 32(n)
    int grp = lane >> 2, thr = lane & 3;

    // staging: 512 16B-segs per tile (128 rows x 4); thread covers rows r0 and r0+64
    int r0 = tid >> 2, c16 = tid & 3;
    uint32_t aS = smem_u32(As), bS = smem_u32(Bs);
    uint32_t off0 = (uint32_t)((r0 * TS2 + c16 * 4) * 4);
    uint32_t off1 = off0 + (uint32_t)(64 * TS2 * 4);
    const __half* aP0 = A + (size_t)r0 * K + c16 * 8;
    const __half* aP1 = aP0 + (size_t)64 * K;
    const __half* bP0 = B + (size_t)r0 * K + c16 * 8;
    const __half* bP1 = bP0 + (size_t)64 * K;

    float acc[4][4][4];
    #pragma unroll
    for (int mf = 0; mf < 4; mf++)
        #pragma unroll
        for (int nf = 0; nf < 4; nf++)
            #pragma unroll
            for (int c = 0; c < 4; c++) acc[mf][nf][c] = 0.f;

    int nk = K / BK;
    auto stage = [&](int kc, int b) {
        uint32_t ad = aS + (uint32_t)(b * BUF32 * 4);
        uint32_t bd = bS + (uint32_t)(b * BUF32 * 4);
        int kh = kc * BK;
        cp16(ad + off0, aP0 + kh);
        cp16(ad + off1, aP1 + kh);
        cp16(bd + off0, bP0 + kh);
        cp16(bd + off1, bP1 + kh);
    };

    stage(0, 0); CP_COMMIT();
    if (nk > 1) stage(1, 1);
    CP_COMMIT();

    int buf = 0;
    for (int kc = 0; kc < nk; kc++) {
        CP_WAIT1();
        __syncthreads();
        int sb = buf + 2; if (sb >= 3) sb -= 3;
        if (kc + 2 < nk) stage(kc + 2, sb);
        CP_COMMIT();

        const uint32_t* Ab = As + buf * BUF32;
        const uint32_t* Bb = Bs + buf * BUF32;
        #pragma unroll
        for (int ks2 = 0; ks2 < 16; ks2 += 8) {    // two K=16 steps (b32 offsets 0, 8)
            uint32_t af[4][4], bf[4][2];
            #pragma unroll
            for (int mf = 0; mf < 4; mf++) {
                int base = (wm * 64 + mf * 16 + grp) * TS2 + ks2 + thr;
                af[mf][0] = Ab[base];
                af[mf][1] = Ab[base + 8 * TS2];
                af[mf][2] = Ab[base + 4];
                af[mf][3] = Ab[base + 8 * TS2 + 4];
            }
            #pragma unroll
            for (int nf = 0; nf < 4; nf++) {
                int base = (wn * 32 + nf * 8 + grp) * TS2 + ks2 + thr;
                bf[nf][0] = Bb[base];
                bf[nf][1] = Bb[base + 4];
            }
            #pragma unroll
            for (int mf = 0; mf < 4; mf++)
                #pragma unroll
                for (int nf = 0; nf < 4; nf++)
                    mma16n8k16(&acc[mf][nf][0], af[mf][0], af[mf][1], af[mf][2], af[mf][3],
                               bf[nf][0], bf[nf][1]);
        }
        buf = buf + 1; if (buf == 3) buf = 0;
    }

    // epilogue: bias (+ SiLU); act=1 -> fp16 store (H), act=0 -> fp32 store (O)
    const float* bias = Ball + (size_t)e * Ntot + (size_t)tile_n * 128;
    #pragma unroll
    for (int mf = 0; mf < 4; mf++) {
        #pragma unroll
        for (int nf = 0; nf < 4; nf++) {
            int row = wm * 64 + mf * 16 + grp;
            int col = wn * 32 + nf * 8 + thr * 2;
            float b0 = bias[col], b1 = bias[col + 1];
            float v00 = acc[mf][nf][0] + b0, v01 = acc[mf][nf][1] + b1;
            float v10 = acc[mf][nf][2] + b0, v11 = acc[mf][nf][3] + b1;
            if (act) {
                v00 = v00 / (1.f + __expf(-v00));
                v01 = v01 / (1.f + __expf(-v01));
                v10 = v10 / (1.f + __expf(-v10));
                v11 = v11 / (1.f + __expf(-v11));
                __half* Cb = (__half*)Cout + (size_t)tile_m * 128 * Ntot + (size_t)tile_n * 128;
                *(__half2*)(Cb + (size_t)row * Ntot + col)       = __floats2half2_rn(v00, v01);
                *(__half2*)(Cb + (size_t)(row + 8) * Ntot + col) = __floats2half2_rn(v10, v11);
            } else {
                float* Cb = (float*)Cout + (size_t)tile_m * 128 * Ntot + (size_t)tile_n * 128;
                *(float2*)(Cb + (size_t)row * Ntot + col)       = make_float2(v00, v01);
                *(float2*)(Cb + (size_t)(row + 8) * Ntot + col) = make_float2(v10, v11);
            }
        }
    }
}

// ---------------- combine ----------------
__global__ void k_combine(float* __restrict__ out, int D) {
    int t = blockIdx.x;
    int rows[SLOT_MAX]; float ws[SLOT_MAX];
    #pragma unroll
    for (int s = 0; s < SLOT_MAX; s++) { rows[s] = g_pos[t*SLOT_MAX+s]; ws[s] = g_wts[t*SLOT_MAX+s]; }
    float4* dst = (float4*)(out + (size_t)t * D);
    for (int c = threadIdx.x; c < (D >> 2); c += blockDim.x) {
        float4 a = make_float4(0.f, 0.f, 0.f, 0.f);
        #pragma unroll
        for (int s = 0; s < SLOT_MAX; s++) {
            if (rows[s] < 0) continue;
            const float4 v = ((const float4*)(g_O + (size_t)rows[s] * D))[c];
            a.x = fmaf(ws[s], v.x, a.x); a.y = fmaf(ws[s], v.y, a.y);
            a.z = fmaf(ws[s], v.z, a.z); a.w = fmaf(ws[s], v.w, a.w);
        }
        dst[c] = a;
    }
}

// ---------------- launch ----------------
extern "C" void kernel_launch(void* const* d_in, const int* in_sizes, int n_in,
                              void* d_out, int out_size) {
    const float* x    = (const float*)d_in[0];
    const float* gw   = (const float*)d_in[1];
    const float* gb   = (const float*)d_in[2];
    const float* w1   = (const float*)d_in[3];
    const float* b1   = (const float*)d_in[4];
    const float* w2   = (const float*)d_in[5];
    const float* b2   = (const float*)d_in[6];
    const int*   topk = (n_in > 7) ? (const int*)d_in[7] : nullptr;
    float* out = (float*)d_out;

    const int E = in_sizes[2];
    const int D = in_sizes[1] / E;
    const int F = in_sizes[4] / E;
    const int T = in_sizes[0] / D;

    __half *Xh = nullptr, *Hh = nullptr, *W1h = nullptr, *W2h = nullptr;
    float  *O  = nullptr;
    cudaGetSymbolAddress((void**)&Xh,  g_Xh);
    cudaGetSymbolAddress((void**)&Hh,  g_Hh);
    cudaGetSymbolAddress((void**)&O,   g_O);
    cudaGetSymbolAddress((void**)&W1h, g_W1h);
    cudaGetSymbolAddress((void**)&W2h, g_W2h);

    cudaFuncSetAttribute(k_gemm_h, cudaFuncAttributeMaxDynamicSharedMemorySize, GSMEM);

    k_init<<<(RPAD_MAX + 255) / 256, 256>>>();
    k_router<<<T, 256>>>(x, gw, gb, topk, D, E);
    k_scan<<<1, 32>>>(E);
    k_assign<<<(T * SLOT_MAX + 255) / 256, 256>>>(T);
    k_gather<<<RPAD_MAX, 256>>>(x, D);

    dim3 bt(32, 8);
    k_wconv<<<dim3(F / 32, D / 32, E), bt>>>(w1, W1h, D, F);   // [E][D][F] -> [E][F][D] fp16
    k_wconv<<<dim3(D / 32, F / 32, E), bt>>>(w2, W2h, F, D);   // [E][F][D] -> [E][D][F] fp16

    k_gemm_h<<<dim3(F / 128, TILES_MAX), 256, GSMEM>>>(Xh, W1h, b1, Hh, F, D, 1);
    k_gemm_h<<<dim3(D / 128, TILES_MAX), 256, GSMEM>>>(Hh, W2h, b2, O, D, F, 0);

    k_combine<<<T, 256>>>(out, D);
}

// round 12
// speedup vs baseline: 2.8779x; 1.0068x over previous
#include <cuda_runtime.h>
#include <cuda_fp16.h>
#include <math.h>
#include <stdint.h>

// ---------------- problem-size maxima (fixed instance: T=4096,D=1024,F=4096,E=8,k=2)
#define T_MAX    4096
#define E_MAX    8
#define SLOT_MAX 2
#define D_MAX    1024
#define F_MAX    4096
#define RPAD_MAX (T_MAX * SLOT_MAX + E_MAX * 128)   // 9216
#define TILES_MAX (RPAD_MAX / 128)                  // 72

// ---------------- device scratch (static: no allocation anywhere)
__device__ __half g_Xh [(size_t)RPAD_MAX * D_MAX];          // gathered tokens, fp16
__device__ __half g_Hh [(size_t)RPAD_MAX * F_MAX];          // hidden, fp16
__device__ float  g_O  [(size_t)RPAD_MAX * D_MAX];          // expert outputs, fp32
__device__ __half g_W1h[(size_t)E_MAX * F_MAX * D_MAX];     // w1^T [E][F][D] fp16
__device__ __half g_W2h[(size_t)E_MAX * D_MAX * F_MAX];     // w2^T [E][D][F] fp16
__device__ int    g_sel [T_MAX * SLOT_MAX];
__device__ float  g_wts [T_MAX * SLOT_MAX];
__device__ int    g_pos [T_MAX * SLOT_MAX];
__device__ int    g_count [E_MAX];
__device__ int    g_cursor[E_MAX];
__device__ int    g_off   [E_MAX + 1];
__device__ int    g_tile2e[TILES_MAX];
__device__ int    g_row2tok[RPAD_MAX];

// ---------------- helpers ----------------
__device__ __forceinline__ uint32_t smem_u32(const void* p) {
    uint32_t a;
    asm("{ .reg .u64 t; cvta.to.shared.u64 t, %1; cvt.u32.u64 %0, t; }" : "=r"(a) : "l"(p));
    return a;
}
__device__ __forceinline__ void cp16(uint32_t dst, const void* src) {
    asm volatile("cp.async.cg.shared.global [%0], [%1], 16;" :: "r"(dst), "l"(src));
}
#define CP_COMMIT() asm volatile("cp.async.commit_group;" ::: "memory")
#define CP_WAIT2()  asm volatile("cp.async.wait_group 2;" ::: "memory")

// fp16 tensor op, baseline target (compiles for compute_103): K=16 per instruction
__device__ __forceinline__ void mma16n8k16(float* c,
                                           uint32_t a0, uint32_t a1, uint32_t a2, uint32_t a3,
                                           uint32_t b0, uint32_t b1) {
    asm volatile(
        "mma.sync.aligned.m16n8k16.row.col.f32.f16.f16.f32 "
        "{%0,%1,%2,%3}, {%4,%5,%6,%7}, {%8,%9}, {%0,%1,%2,%3};"
        : "+f"(c[0]), "+f"(c[1]), "+f"(c[2]), "+f"(c[3])
        : "r"(a0), "r"(a1), "r"(a2), "r"(a3), "r"(b0), "r"(b1));
}

// ---------------- init ----------------
__global__ void k_init() {
    int i = blockIdx.x * blockDim.x + threadIdx.x;
    if (i < RPAD_MAX)  g_row2tok[i] = -1;
    if (i < TILES_MAX) g_tile2e[i]  = -1;
    if (i < E_MAX)   { g_count[i] = 0; g_cursor[i] = 0; }
}

// ---------------- router ----------------
__global__ void k_router(const float* __restrict__ x, const float* __restrict__ gw,
                         const float* __restrict__ gb, const int* __restrict__ topk_p,
                         int D, int E) {
    int t = blockIdx.x;
    float acc[E_MAX];
    #pragma unroll
    for (int e = 0; e < E_MAX; e++) acc[e] = 0.f;
    const float* xr = x + (size_t)t * D;
    for (int d = threadIdx.x; d < D; d += blockDim.x) {
        float xv = xr[d];
        for (int e = 0; e < E; e++) acc[e] += xv * gw[(size_t)e * D + d];
    }
    __shared__ float sred[E_MAX][8];
    int lane = threadIdx.x & 31, wid = threadIdx.x >> 5;
    for (int e = 0; e < E; e++) {
        float v = acc[e];
        #pragma unroll
        for (int o = 16; o > 0; o >>= 1) v += __shfl_down_sync(0xffffffffu, v, o);
        if (lane == 0) sred[e][wid] = v;
    }
    __syncthreads();
    if (threadIdx.x == 0) {
        int nw = blockDim.x >> 5;
        float logit[E_MAX], mx = -1e30f;
        for (int e = 0; e < E; e++) {
            float s = gb[e];
            for (int w = 0; w < nw; w++) s += sred[e][w];
            logit[e] = s; mx = fmaxf(mx, s);
        }
        float p[E_MAX], Z = 0.f;
        for (int e = 0; e < E; e++) { p[e] = expf(logit[e] - mx); Z += p[e]; }
        float invZ = 1.f / Z;
        for (int e = 0; e < E; e++) p[e] *= invZ;

        int k = topk_p ? *topk_p : 2;
        if (k > SLOT_MAX) k = SLOT_MAX;
        if (k < 1) k = 1;
        bool used[E_MAX];
        for (int e = 0; e < E; e++) used[e] = false;
        float wsum = 0.f;
        int sels[SLOT_MAX]; float wv[SLOT_MAX];
        for (int s = 0; s < k; s++) {
            int best = 0; float bv = -1.f;
            for (int e = 0; e < E; e++)
                if (!used[e] && p[e] > bv) { bv = p[e]; best = e; }  // strict > => lowest idx on tie
            used[best] = true;
            sels[s] = best; wv[s] = bv; wsum += bv;
            atomicAdd(&g_count[best], 1);
        }
        float inv = 1.f / wsum;
        for (int s = 0; s < k; s++) { g_sel[t*SLOT_MAX+s] = sels[s]; g_wts[t*SLOT_MAX+s] = wv[s]*inv; }
        for (int s = k; s < SLOT_MAX; s++) { g_sel[t*SLOT_MAX+s] = -1; g_wts[t*SLOT_MAX+s] = 0.f; }
    }
}

// ---------------- scan ----------------
__global__ void k_scan(int E) {
    if (threadIdx.x != 0 || blockIdx.x != 0) return;
    int off = 0;
    for (int e = 0; e < E; e++) {
        g_off[e] = off;
        int tiles = (g_count[e] + 127) >> 7;
        for (int i = 0; i < tiles; i++) g_tile2e[(off >> 7) + i] = e;
        off += tiles << 7;
    }
    g_off[E] = off;
}

// ---------------- assign ----------------
__global__ void k_assign(int T) {
    int idx = blockIdx.x * blockDim.x + threadIdx.x;
    if (idx >= T * SLOT_MAX) return;
    int t = idx / SLOT_MAX, s = idx % SLOT_MAX;
    int e = g_sel[t * SLOT_MAX + s];
    if (e < 0) { g_pos[t * SLOT_MAX + s] = -1; return; }
    int pos = atomicAdd(&g_cursor[e], 1);
    int row = g_off[e] + pos;
    g_row2tok[row] = t;
    g_pos[t * SLOT_MAX + s] = row;
}

// ---------------- gather: fp32 tokens -> fp16 rows (zeros for pad) ----------------
__global__ void k_gather(const float* __restrict__ x, int D) {
    int row = blockIdx.x;
    int tok = g_row2tok[row];
    __half2* dst = (__half2*)(g_Xh + (size_t)row * D);
    if (tok >= 0) {
        const float2* src = (const float2*)(x + (size_t)tok * D);
        for (int c = threadIdx.x; c < (D >> 1); c += blockDim.x) {
            float2 v = src[c];
            dst[c] = __floats2half2_rn(v.x, v.y);
        }
    } else {
        __half2 z = __floats2half2_rn(0.f, 0.f);
        for (int c = threadIdx.x; c < (D >> 1); c += blockDim.x) dst[c] = z;
    }
}

// ---------------- weight convert+transpose: fp32 [E][K][N] -> fp16 [E][N][K] ----------------
__global__ void k_wconv(const float* __restrict__ W, __half* __restrict__ Wt, int K, int N) {
    __shared__ float t[32][33];
    int e = blockIdx.z;
    const float* We = W + (size_t)e * K * N;
    __half* Wte = Wt + (size_t)e * N * K;
    int n0 = blockIdx.x * 32, k0 = blockIdx.y * 32;
    #pragma unroll
    for (int i = 0; i < 32; i += 8) {
        int k = k0 + threadIdx.y + i;
        t[threadIdx.y + i][threadIdx.x] = We[(size_t)k * N + n0 + threadIdx.x];
    }
    __syncthreads();
    #pragma unroll
    for (int i = 0; i < 32; i += 8) {
        int n = n0 + threadIdx.y + i;
        Wte[(size_t)n * K + k0 + threadIdx.x] = __float2half_rn(t[threadIdx.x][threadIdx.y + i]);
    }
}

// ---------------- fp16 tensor GEMM: 128x128 tile, m16n8k16, cp.async 4-stage ----------------
// A: [rows][K] halfs k-contig; Wt: [E][Ntot][K] halfs k-contig; bias: [E][Ntot] fp32;
// act=1 -> silu, store fp16 (H);  act=0 -> store fp32 (O). C row stride Ntot.
#define BK  32                  // halfs per chunk = 64B rows
#define TS2 20                  // smem row stride in b32 (16 data + 4 pad): lanes g*20+t -> 32 banks
#define BUF32 (128 * TS2)       // b32 per buffer (A or B) = 2560 -> 10240 B
#define GSMEM (8 * BUF32 * 4)   // 4 A + 4 B buffers = 81920 B

__global__ void __launch_bounds__(256, 2)
k_gemm_h(const __half* __restrict__ Abase, const __half* __restrict__ Wt,
         const float* __restrict__ Ball, void* __restrict__ Cout,
         int Ntot, int K, int act) {
    int tile_m = blockIdx.y, tile_n = blockIdx.x;
    int e = g_tile2e[tile_m];
    if (e < 0) return;

    extern __shared__ uint32_t smu[];
    uint32_t* As = smu;                  // [4][128][TS2]
    uint32_t* Bs = smu + 4 * BUF32;      // [4][128][TS2]

    const __half* A = Abase + (size_t)tile_m * 128 * K;
    const __half* B = Wt + (size_t)e * Ntot * K + (size_t)tile_n * 128 * K;  // [n][k]

    int tid = threadIdx.x, lane = tid & 31, wid = tid >> 5;
    int wm = wid & 1, wn = wid >> 1;     // warp tile 64(m) x 32(n)
    int grp = lane >> 2, thr = lane & 3;

    // staging: 512 16B-segs per tile (128 rows x 4); thread covers rows r0 and r0+64
    int r0 = tid >> 2, c16 = tid & 3;
    uint32_t aS = smem_u32(As), bS = smem_u32(Bs);
    uint32_t off0 = (uint32_t)((r0 * TS2 + c16 * 4) * 4);
    uint32_t off1 = off0 + (uint32_t)(64 * TS2 * 4);
    const __half* aP0 = A + (size_t)r0 * K + c16 * 8;
    const __half* aP1 = aP0 + (size_t)64 * K;
    const __half* bP0 = B + (size_t)r0 * K + c16 * 8;
    const __half* bP1 = bP0 + (size_t)64 * K;

    float acc[4][4][4];
    #pragma unroll
    for (int mf = 0; mf < 4; mf++)
        #pragma unroll
        for (int nf = 0; nf < 4; nf++)
            #pragma unroll
            for (int c = 0; c < 4; c++) acc[mf][nf][c] = 0.f;

    int nk = K / BK;
    auto stage = [&](int kc, int b) {
        uint32_t ad = aS + (uint32_t)(b * BUF32 * 4);
        uint32_t bd = bS + (uint32_t)(b * BUF32 * 4);
        int kh = kc * BK;
        cp16(ad + off0, aP0 + kh);
        cp16(ad + off1, aP1 + kh);
        cp16(bd + off0, bP0 + kh);
        cp16(bd + off1, bP1 + kh);
    };

    // prologue: prefetch depth 3
    stage(0, 0); CP_COMMIT();
    if (nk > 1) stage(1, 1);
    CP_COMMIT();
    if (nk > 2) stage(2, 2);
    CP_COMMIT();

    int buf = 0;
    for (int kc = 0; kc < nk; kc++) {
        CP_WAIT2();                      // chunk kc landed (≤2 groups still in flight)
        __syncthreads();
        int sb = (buf + 3) & 3;
        if (kc + 3 < nk) stage(kc + 3, sb);
        CP_COMMIT();

        const uint32_t* Ab = As + buf * BUF32;
        const uint32_t* Bb = Bs + buf * BUF32;
        #pragma unroll
        for (int ks2 = 0; ks2 < 16; ks2 += 8) {    // two K=16 steps (b32 offsets 0, 8)
            uint32_t af[4][4], bf[4][2];
            #pragma unroll
            for (int mf = 0; mf < 4; mf++) {
                int base = (wm * 64 + mf * 16 + grp) * TS2 + ks2 + thr;
                af[mf][0] = Ab[base];
                af[mf][1] = Ab[base + 8 * TS2];
                af[mf][2] = Ab[base + 4];
                af[mf][3] = Ab[base + 8 * TS2 + 4];
            }
            #pragma unroll
            for (int nf = 0; nf < 4; nf++) {
                int base = (wn * 32 + nf * 8 + grp) * TS2 + ks2 + thr;
                bf[nf][0] = Bb[base];
                bf[nf][1] = Bb[base + 4];
            }
            #pragma unroll
            for (int mf = 0; mf < 4; mf++)
                #pragma unroll
                for (int nf = 0; nf < 4; nf++)
                    mma16n8k16(&acc[mf][nf][0], af[mf][0], af[mf][1], af[mf][2], af[mf][3],
                               bf[nf][0], bf[nf][1]);
        }
        buf = (buf + 1) & 3;
    }

    // epilogue: bias (+ SiLU); act=1 -> fp16 store (H), act=0 -> fp32 store (O)
    const float* bias = Ball + (size_t)e * Ntot + (size_t)tile_n * 128;
    #pragma unroll
    for (int mf = 0; mf < 4; mf++) {
        #pragma unroll
        for (int nf = 0; nf < 4; nf++) {
            int row = wm * 64 + mf * 16 + grp;
            int col = wn * 32 + nf * 8 + thr * 2;
            float b0 = bias[col], b1 = bias[col + 1];
            float v00 = acc[mf][nf][0] + b0, v01 = acc[mf][nf][1] + b1;
            float v10 = acc[mf][nf][2] + b0, v11 = acc[mf][nf][3] + b1;
            if (act) {
                v00 = v00 / (1.f + __expf(-v00));
                v01 = v01 / (1.f + __expf(-v01));
                v10 = v10 / (1.f + __expf(-v10));
                v11 = v11 / (1.f + __expf(-v11));
                __half* Cb = (__half*)Cout + (size_t)tile_m * 128 * Ntot + (size_t)tile_n * 128;
                *(__half2*)(Cb + (size_t)row * Ntot + col)       = __floats2half2_rn(v00, v01);
                *(__half2*)(Cb + (size_t)(row + 8) * Ntot + col) = __floats2half2_rn(v10, v11);
            } else {
                float* Cb = (float*)Cout + (size_t)tile_m * 128 * Ntot + (size_t)tile_n * 128;
                *(float2*)(Cb + (size_t)row * Ntot + col)       = make_float2(v00, v01);
                *(float2*)(Cb + (size_t)(row + 8) * Ntot + col) = make_float2(v10, v11);
            }
        }
    }
}

// ---------------- combine ----------------
__global__ void k_combine(float* __restrict__ out, int D) {
    int t = blockIdx.x;
    int rows[SLOT_MAX]; float ws[SLOT_MAX];
    #pragma unroll
    for (int s = 0; s < SLOT_MAX; s++) { rows[s] = g_pos[t*SLOT_MAX+s]; ws[s] = g_wts[t*SLOT_MAX+s]; }
    float4* dst = (float4*)(out + (size_t)t * D);
    for (int c = threadIdx.x; c < (D >> 2); c += blockDim.x) {
        float4 a = make_float4(0.f, 0.f, 0.f, 0.f);
        #pragma unroll
        for (int s = 0; s < SLOT_MAX; s++) {
            if (rows[s] < 0) continue;
            const float4 v = ((const float4*)(g_O + (size_t)rows[s] * D))[c];
            a.x = fmaf(ws[s], v.x, a.x); a.y = fmaf(ws[s], v.y, a.y);
            a.z = fmaf(ws[s], v.z, a.z); a.w = fmaf(ws[s], v.w, a.w);
        }
        dst[c] = a;
    }
}

// ---------------- launch ----------------
extern "C" void kernel_launch(void* const* d_in, const int* in_sizes, int n_in,
                              void* d_out, int out_size) {
    const float* x    = (const float*)d_in[0];
    const float* gw   = (const float*)d_in[1];
    const float* gb   = (const float*)d_in[2];
    const float* w1   = (const float*)d_in[3];
    const float* b1   = (const float*)d_in[4];
    const float* w2   = (const float*)d_in[5];
    const float* b2   = (const float*)d_in[6];
    const int*   topk = (n_in > 7) ? (const int*)d_in[7] : nullptr;
    float* out = (float*)d_out;

    const int E = in_sizes[2];
    const int D = in_sizes[1] / E;
    const int F = in_sizes[4] / E;
    const int T = in_sizes[0] / D;

    __half *Xh = nullptr, *Hh = nullptr, *W1h = nullptr, *W2h = nullptr;
    float  *O  = nullptr;
    cudaGetSymbolAddress((void**)&Xh,  g_Xh);
    cudaGetSymbolAddress((void**)&Hh,  g_Hh);
    cudaGetSymbolAddress((void**)&O,   g_O);
    cudaGetSymbolAddress((void**)&W1h, g_W1h);
    cudaGetSymbolAddress((void**)&W2h, g_W2h);

    cudaFuncSetAttribute(k_gemm_h, cudaFuncAttributeMaxDynamicSharedMemorySize, GSMEM);

    // side stream + events: created once on the first (uncaptured) correctness call;
    // during capture only EventRecord/StreamWaitEvent/launches are issued (all capturable).
    static cudaStream_t s_side = nullptr;
    static cudaEvent_t  s_fork = nullptr, s_w1 = nullptr, s_w2 = nullptr;
    if (!s_side) {
        cudaStreamCreateWithFlags(&s_side, cudaStreamNonBlocking);
        cudaEventCreateWithFlags(&s_fork, cudaEventDisableTiming);
        cudaEventCreateWithFlags(&s_w1,   cudaEventDisableTiming);
        cudaEventCreateWithFlags(&s_w2,   cudaEventDisableTiming);
    }

    dim3 bt(32, 8);

    // fork: weight conversion runs on the side stream
    cudaEventRecord(s_fork, 0);
    cudaStreamWaitEvent(s_side, s_fork, 0);
    k_wconv<<<dim3(F / 32, D / 32, E), bt, 0, s_side>>>(w1, W1h, D, F);  // [E][D][F]->[E][F][D]
    cudaEventRecord(s_w1, s_side);
    k_wconv<<<dim3(D / 32, F / 32, E), bt, 0, s_side>>>(w2, W2h, F, D);  // [E][F][D]->[E][D][F]
    cudaEventRecord(s_w2, s_side);

    // main stream: routing pipeline (independent of weights)
    k_init<<<(RPAD_MAX + 255) / 256, 256>>>();
    k_router<<<T, 256>>>(x, gw, gb, topk, D, E);
    k_scan<<<1, 32>>>(E);
    k_assign<<<(T * SLOT_MAX + 255) / 256, 256>>>(T);
    k_gather<<<RPAD_MAX, 256>>>(x, D);

    // join 1: GEMM1 needs W1h (wconv2 keeps running under GEMM1)
    cudaStreamWaitEvent(0, s_w1, 0);
    k_gemm_h<<<dim3(F / 128, TILES_MAX), 256, GSMEM>>>(Xh, W1h, b1, Hh, F, D, 1);

    // join 2: GEMM2 needs W2h
    cudaStreamWaitEvent(0, s_w2, 0);
    k_gemm_h<<<dim3(D / 128, TILES_MAX), 256, GSMEM>>>(Hh, W2h, b2, O, D, F, 0);

    k_combine<<<T, 256>>>(out, D);
}